// round 17
// baseline (speedup 1.0000x reference)
#include <cuda_runtime.h>

// Shapes (fixed)
#define Bn 16
#define In 32
#define Cn 8
#define Jn 10
#define Dn 16
#define Xn 576   // D*H*W
#define NT 576   // threads per CTA (18 warps); thread owns one x per slice
#define HWn 36
#define EPSf 1e-7f
#define SL 2     // j-slices per CTA
#define GRIDP (Bn*Jn/SL)   // 80 CTAs; 1/SM co-residency (112 regs, 18 warps/SM)

// Cross-CTA comm scratch, parity double-buffered (WAR-safe across the single
// per-iteration grid barrier; protocol validated R9/R16).
__device__ float    g_nPart[2][Bn*Jn];        // [b*Jn + j]
__device__ float    g_aPart[2][Bn*Jn*In];     // [entry][i], 128B coalesced rows
__device__ unsigned g_cnt;
__device__ unsigned g_gen;

__device__ __forceinline__ float squash_k(float n) {
    float n2 = n * n;
    return (n2 / (1.f + n2)) / (n + EPSf);
}

// Flat grid barrier; 80 arrivals. All 80 CTAs co-resident at 1/SM.
__device__ __forceinline__ void gridBarrier() {
    __threadfence();
    __syncthreads();
    if (threadIdx.x == 0) {
        unsigned g0 = *(volatile unsigned*)&g_gen;
        unsigned a = atomicAdd(&g_cnt, 1u);
        if (a == GRIDP - 1) {
            atomicExch(&g_cnt, 0u);
            __threadfence();
            atomicAdd(&g_gen, 1u);
        } else {
            while (*(volatile unsigned*)&g_gen == g0) { }
        }
        __threadfence();
    }
    __syncthreads();
}

__global__ void __launch_bounds__(NT, 1) routing_all(
    const float* __restrict__ u, const float* __restrict__ bias,
    float* __restrict__ out)
{
    // two U tiles (one per j-slice): 2 x 32 x 576 floats = 147,456 B dynamic
    extern __shared__ __align__(16) float Us[];   // Us[s*In*Xn + i*Xn + x]
    __shared__ float ss[SL][Xn];
    __shared__ float sb[In * Jn];     // routing logits (identical in all CTAs)
    __shared__ float cs[SL][In];      // coupling coeffs for this CTA's two j's
    __shared__ float kb_sh[Bn];
    __shared__ float red[SL][18];
    int b  = blockIdx.x / (Jn / SL);
    int j0 = (blockIdx.x % (Jn / SL)) * SL;
    int bj0 = b * Jn + j0;
    int x = threadIdx.x;
    int w = x >> 5, lane = x & 31;
    int d = x / HWn;                  // x in 0..575 -> depth index

    for (int t = x; t < In * Jn; t += NT) sb[t] = 0.f;

    // ---- Load phase: Us[s][i][x] = sum_c u_hat[b,i,c,j0+s,x].
    // 94 MB total; 18 warps/SM, 112-reg budget, 8-deep float4 batching.
    {
        int t4 = x % 144, g = x / 144;        // 4 i-groups x 144 float4-cols
        int xq = t4 * 4;
        #pragma unroll
        for (int s = 0; s < SL; s++) {
            const float* base = u + (size_t)b * In * Cn * Jn * Xn
                                  + (size_t)(j0 + s) * Xn + xq;
            float* us = Us + s * In * Xn;
            #pragma unroll 2
            for (int ii = 0; ii < 8; ii++) {
                int i = g * 8 + ii;
                const float4* p = (const float4*)(base + (size_t)i * Cn * Jn * Xn);
                float4 a0 = __ldcs(p);
                float4 a1 = __ldcs(p + 1 * (Jn * Xn / 4));
                float4 a2 = __ldcs(p + 2 * (Jn * Xn / 4));
                float4 a3 = __ldcs(p + 3 * (Jn * Xn / 4));
                float4 a4 = __ldcs(p + 4 * (Jn * Xn / 4));
                float4 a5 = __ldcs(p + 5 * (Jn * Xn / 4));
                float4 a6 = __ldcs(p + 6 * (Jn * Xn / 4));
                float4 a7 = __ldcs(p + 7 * (Jn * Xn / 4));
                float4 acc;
                acc.x = ((a0.x + a1.x) + (a2.x + a3.x)) + ((a4.x + a5.x) + (a6.x + a7.x));
                acc.y = ((a0.y + a1.y) + (a2.y + a3.y)) + ((a4.y + a5.y) + (a6.y + a7.y));
                acc.z = ((a0.z + a1.z) + (a2.z + a3.z)) + ((a4.z + a5.z) + (a6.z + a7.z));
                acc.w = ((a0.w + a1.w) + (a2.w + a3.w)) + ((a4.w + a5.w) + (a6.w + a7.w));
                *(float4*)&us[i * Xn + xq] = acc;
            }
        }
    }
    __syncthreads();

    float sv0 = 0.f, sv1 = 0.f;       // s for slice 0 / slice 1 at this x
    #pragma unroll 1
    for (int iter = 0; iter < 3; iter++) {
        int pb = iter & 1;

        // ---- routing update (iter > 0): coalesced, lane = i, 128B rows.
        if (iter > 0) {
            int prev = (iter - 1) & 1;
            if (x < Bn) {
                float nn = 0.f;
                #pragma unroll
                for (int t = 0; t < Jn; t++) nn += __ldcg(&g_nPart[prev][x * Jn + t]);
                kb_sh[x] = squash_k(nn);
            }
            __syncthreads();
            if (w < Jn) {                       // warp w owns j = w
                float a = 0.f;
                #pragma unroll
                for (int bb = 0; bb < Bn; bb++) {
                    int ent = bb * Jn + w;
                    a += kb_sh[bb] * __ldcg(&g_aPart[prev][(size_t)ent * In + lane]);
                }
                sb[lane * Jn + w] += a;         // b_ij += agreement
            }
            __syncthreads();
            if (x < In) {
                float mx = -1e30f;
                #pragma unroll
                for (int jj = 0; jj < Jn; jj++) mx = fmaxf(mx, sb[x * Jn + jj]);
                float den = 0.f;
                #pragma unroll
                for (int jj = 0; jj < Jn; jj++) den += __expf(sb[x * Jn + jj] - mx);
                cs[0][x] = __expf(sb[x * Jn + j0]     - mx) / den;
                cs[1][x] = __expf(sb[x * Jn + j0 + 1] - mx) / den;
            }
            __syncthreads();
        }

        // ---- s for both slices at this x
        if (iter == 0) {
            float a0 = 0.f, a1 = 0.f;
            #pragma unroll
            for (int i = 0; i < In; i++) {
                a0 += Us[0 * In * Xn + i * Xn + x];
                a1 += Us[1 * In * Xn + i * Xn + x];
            }
            sv0 = a0 * (1.0f / Jn) + bias[j0 * Dn + d];       // softmax(0)=1/J
            sv1 = a1 * (1.0f / Jn) + bias[(j0 + 1) * Dn + d];
        } else {
            float a0 = 0.f, a1 = 0.f;
            #pragma unroll
            for (int i = 0; i < In; i++) {
                a0 += cs[0][i] * Us[0 * In * Xn + i * Xn + x];
                a1 += cs[1][i] * Us[1 * In * Xn + i * Xn + x];
            }
            sv0 = a0 + bias[j0 * Dn + d];
            sv1 = a1 + bias[(j0 + 1) * Dn + d];
        }
        // ---- L1-norms (both slices; 18-warp block reduction)
        {
            float v0 = fabsf(sv0), v1 = fabsf(sv1);
            #pragma unroll
            for (int o = 16; o > 0; o >>= 1) {
                v0 += __shfl_down_sync(0xffffffffu, v0, o);
                v1 += __shfl_down_sync(0xffffffffu, v1, o);
            }
            if (lane == 0) { red[0][w] = v0; red[1][w] = v1; }
            __syncthreads();
            if (x == 0) {
                float n0 = 0.f, n1 = 0.f;
                #pragma unroll
                for (int k = 0; k < 18; k++) { n0 += red[0][k]; n1 += red[1][k]; }
                g_nPart[pb][bj0]     = n0;
                g_nPart[pb][bj0 + 1] = n1;
            }
        }

        if (iter == 2) break;                   // final agreement is dead

        ss[0][x] = sv0;
        ss[1][x] = sv1;
        __syncthreads();
        // ---- unscaled agreement: warps 0..15 -> (slice = w>>3, 4 i's each)
        if (w < 16) {
            int s = w >> 3;
            const float* us = Us + s * In * Xn;
            const float* sv = ss[s];
            #pragma unroll
            for (int ii = 0; ii < 4; ii++) {
                int i = (w & 7) * 4 + ii;
                float a = 0.f;
                #pragma unroll
                for (int xx = lane; xx < Xn; xx += 32) a += us[i * Xn + xx] * sv[xx];
                #pragma unroll
                for (int o = 16; o > 0; o >>= 1) a += __shfl_down_sync(0xffffffffu, a, o);
                if (lane == 0) g_aPart[pb][(size_t)(bj0 + s) * In + i] = a;
            }
        }
        gridBarrier();
    }

    // ---- final squash (iter-2 norms in buffer 0); kb depends only on b
    gridBarrier();
    if (x < 32) {
        float v = (lane < Jn) ? __ldcg(&g_nPart[0][b * Jn + lane]) : 0.f;
        #pragma unroll
        for (int o = 16; o > 0; o >>= 1) v += __shfl_down_sync(0xffffffffu, v, o);
        if (lane == 0) kb_sh[0] = squash_k(v);
    }
    __syncthreads();
    float kb = kb_sh[0];
    out[(size_t)bj0 * Xn + x]        = kb * sv0;
    out[(size_t)(bj0 + 1) * Xn + x]  = kb * sv1;
}

extern "C" void kernel_launch(void* const* d_in, const int* in_sizes, int n_in,
                              void* d_out, int out_size) {
    const float* u    = (const float*)d_in[0];
    const float* bias = (const float*)d_in[1];
    float* out = (float*)d_out;
    const int dyn_smem = SL * In * Xn * sizeof(float);   // 147,456 B
    cudaFuncSetAttribute(routing_all,
                         cudaFuncAttributeMaxDynamicSharedMemorySize, dyn_smem);
    routing_all<<<GRIDP, NT, dyn_smem>>>(u, bias, out);
}